// round 14
// baseline (speedup 1.0000x reference)
#include <cuda_runtime.h>

// Problem constants (fixed by reference setup_inputs: B=2, N=1024, K=64, R=0.15)
#define NPTS   1024
#define NBATCH 2
#define NQ     (NBATCH * NPTS)     // 2048 queries
#define KNB    64
#define RADIUS2 0.0225f
#define NVAR   10                  // distinct nonzero diag variants

// Static device scratch (no allocation allowed)
__device__ float g_gp[NQ * 3 * KNB];        // SoA relative coords, zero-padded: [q][xyz][64]
__device__ int   g_cnt[NQ];                 // in-ball neighbor count per query
__device__ float g_m[NVAR * NQ * 64];       // per-variant per-query max over neighbors, 64 ch

// ---------------------------------------------------------------------------
// Kernel 1: ball gather. One thread per query, all support points in smem.
// Exact top-64-smallest-d2 within radius (replace-max path for cnt>64).
// Padding with zeros is exact: self (g=0) is always an in-ball neighbor.
// ---------------------------------------------------------------------------
__global__ void __launch_bounds__(128) gather_kernel(const float* __restrict__ x) {
    __shared__ float ysx[NPTS], ysy[NPTS], ysz[NPTS];
    int b = blockIdx.x >> 3;                    // 8 blocks of 128 per batch
    const float* xb = x + b * NPTS * 3;
    for (int i = threadIdx.x; i < NPTS; i += blockDim.x) {
        ysx[i] = xb[i * 3 + 0];
        ysy[i] = xb[i * 3 + 1];
        ysz[i] = xb[i * 3 + 2];
    }
    __syncthreads();

    int n = ((blockIdx.x & 7) << 7) + threadIdx.x;
    int q = b * NPTS + n;
    float qx = ysx[n], qy = ysy[n], qz = ysz[n];

    float dds[KNB];
    int cnt = 0;
    float* gq = g_gp + q * (3 * KNB);

    for (int m = 0; m < NPTS; m++) {
        float dx = ysx[m] - qx;
        float dy = ysy[m] - qy;
        float dz = ysz[m] - qz;
        // match XLA rounding: squares and adds, no FMA contraction
        float d2 = __fadd_rn(__fadd_rn(__fmul_rn(dx, dx), __fmul_rn(dy, dy)),
                             __fmul_rn(dz, dz));
        if (d2 <= RADIUS2) {
            if (cnt < KNB) {
                dds[cnt] = d2;
                gq[cnt]           = dx;
                gq[KNB + cnt]     = dy;
                gq[2 * KNB + cnt] = dz;
                cnt++;
            } else {
                // exact: keep the 64 smallest d2 (rare path; never triggers on
                // uniform data with E[cnt]~15, but correctness-preserving)
                float mx = -1.0f; int mi = 0;
                for (int t = 0; t < KNB; t++)
                    if (dds[t] > mx) { mx = dds[t]; mi = t; }
                if (d2 < mx) {
                    dds[mi] = d2;
                    gq[mi]           = dx;
                    gq[KNB + mi]     = dy;
                    gq[2 * KNB + mi] = dz;
                }
            }
        }
    }
    for (int t = cnt; t < KNB; t++) {
        gq[t] = 0.0f; gq[KNB + t] = 0.0f; gq[2 * KNB + t] = 0.0f;
    }
    g_cnt[q] = cnt;
}

// ---------------------------------------------------------------------------
// Kernel 2: per-(query, variant) MLP + max over real neighbors.
// One warp per (q, v). Lane = channel for layer1, lane = 2 output channels
// (W2 rows in registers) for layer2. h1 distributed via shuffles.
// Deterministic: no atomics, no cross-lane float reduction.
// ---------------------------------------------------------------------------
__global__ void __launch_bounds__(256) mlp_kernel(const float* __restrict__ W1,
                                                  const float* __restrict__ b1,
                                                  const float* __restrict__ W2,
                                                  const float* __restrict__ b2) {
    __shared__ float sW2[64 * 32];
    __shared__ float sW1[32 * 3];
    __shared__ float sb1[32];
    __shared__ float sb2[64];

    int tid = threadIdx.x;
    for (int i = tid; i < 64 * 32; i += 256) sW2[i] = W2[i];
    if (tid < 96) sW1[tid] = W1[tid];
    if (tid < 32) sb1[tid] = b1[tid];
    if (tid < 64) sb2[tid] = b2[tid];
    __syncthreads();

    int warp = blockIdx.x * 8 + (tid >> 5);      // 0 .. 20479
    int q = warp / NVAR;
    int v = warp - q * NVAR;
    int lane = tid & 31;

    // diag variants: 4 full (weight 1), 6 single-axis (weight 2) — weights in combine
    const float DX[NVAR] = { 1.f, 1.f,-1.f,-1.f,  1.f,-1.f, 0.f, 0.f, 0.f, 0.f };
    const float DY[NVAR] = { 1.f,-1.f, 1.f,-1.f,  0.f, 0.f, 1.f,-1.f, 0.f, 0.f };
    const float DZ[NVAR] = { 1.f,-1.f,-1.f, 1.f,  0.f, 0.f, 0.f, 0.f, 1.f,-1.f };
    float sx = DX[v], sy = DY[v], sz = DZ[v];

    // layer1: lane = channel; fold diag sign into W1 row
    float a0  = sx * sW1[lane * 3 + 0];
    float a1  = sy * sW1[lane * 3 + 1];
    float a2  = sz * sW1[lane * 3 + 2];
    float b1l = sb1[lane];

    // layer2: lane owns output channels (lane, lane+32); W2 rows in registers
    float w2a[32], w2b[32];
#pragma unroll
    for (int c = 0; c < 32; c++) {
        w2a[c] = sW2[lane * 32 + c];
        w2b[c] = sW2[(lane + 32) * 32 + c];
    }
    float bo0 = sb2[lane], bo1 = sb2[lane + 32];

    int cnt = g_cnt[q];
    const float* gq = g_gp + q * (3 * KNB);

    float m0 = 0.0f, m1 = 0.0f;   // relu outputs are >= 0 and self (g=0) is in set

    // lane-preloaded neighbor coords, batch of 32
    float rgx = gq[lane], rgy = gq[KNB + lane], rgz = gq[2 * KNB + lane];

    for (int j0 = 0; j0 < cnt; j0 += 32) {
        if (j0) {   // second batch (cnt > 32, rare)
            rgx = gq[32 + lane];
            rgy = gq[KNB + 32 + lane];
            rgz = gq[2 * KNB + 32 + lane];
        }
        int jend = cnt - j0; if (jend > 32) jend = 32;
        for (int j = 0; j < jend; j++) {
            float gx = __shfl_sync(0xffffffffu, rgx, j);
            float gy = __shfl_sync(0xffffffffu, rgy, j);
            float gz = __shfl_sync(0xffffffffu, rgz, j);
            // layer1, channel = lane
            float h1 = fmaxf(fmaf(gx, a0, fmaf(gy, a1, fmaf(gz, a2, b1l))), 0.0f);
            // layer2: broadcast h1 over channels via shuffle, 4 accumulator chains
            float acc0a = bo0, acc0b = 0.0f, acc1a = bo1, acc1b = 0.0f;
#pragma unroll
            for (int c = 0; c < 32; c += 2) {
                float hc0 = __shfl_sync(0xffffffffu, h1, c);
                float hc1 = __shfl_sync(0xffffffffu, h1, c + 1);
                acc0a = fmaf(hc0, w2a[c],     acc0a);
                acc1a = fmaf(hc0, w2b[c],     acc1a);
                acc0b = fmaf(hc1, w2a[c + 1], acc0b);
                acc1b = fmaf(hc1, w2b[c + 1], acc1b);
            }
            float r0 = fmaxf(acc0a + acc0b, 0.0f);
            float r1 = fmaxf(acc1a + acc1b, 0.0f);
            m0 = fmaxf(m0, r0);
            m1 = fmaxf(m1, r1);
        }
    }

    float* mo = g_m + (v * NQ + q) * 64;
    mo[lane]      = m0;
    mo[lane + 32] = m1;
}

// ---------------------------------------------------------------------------
// Kernel 3: combine. f[b,o,n] = (8*c0[o] + sum_v w_v * m[v,q,o]) / 24
// c0 = relu(W2 relu(b1) + b2): the output for the 8 zero-diagonal rotations.
// ---------------------------------------------------------------------------
__global__ void __launch_bounds__(256) combine_kernel(const float* __restrict__ b1,
                                                      const float* __restrict__ W2,
                                                      const float* __restrict__ b2,
                                                      float* __restrict__ out) {
    __shared__ float h1b[32];
    __shared__ float c0s[64];
    int tid = threadIdx.x;
    if (tid < 32) h1b[tid] = fmaxf(b1[tid], 0.0f);
    __syncthreads();
    if (tid < 64) {
        float a = b2[tid];
#pragma unroll
        for (int c = 0; c < 32; c++) a = fmaf(W2[tid * 32 + c], h1b[c], a);
        c0s[tid] = 8.0f * fmaxf(a, 0.0f);
    }
    __syncthreads();

    const float WV[NVAR] = { 1.f, 1.f, 1.f, 1.f, 2.f, 2.f, 2.f, 2.f, 2.f, 2.f };

    int i = blockIdx.x * 256 + tid;      // 0 .. 131071  (= NQ*64)
    int q = i >> 6;
    int o = i & 63;
    float f = c0s[o];
#pragma unroll
    for (int v = 0; v < NVAR; v++)
        f += WV[v] * g_m[(v * NQ + q) * 64 + o];

    int b = q >> 10;
    int n = q & 1023;
    out[(b * 64 + o) * NPTS + n] = f * (1.0f / 24.0f);
}

// ---------------------------------------------------------------------------
extern "C" void kernel_launch(void* const* d_in, const int* in_sizes, int n_in,
                              void* d_out, int out_size) {
    const float* x  = (const float*)d_in[0];   // [2,1024,3]
    const float* W1 = (const float*)d_in[1];   // [32,3]
    const float* b1 = (const float*)d_in[2];   // [32]
    const float* W2 = (const float*)d_in[3];   // [64,32]
    const float* b2 = (const float*)d_in[4];   // [64]
    float* out = (float*)d_out;                // [2,64,1024]

    gather_kernel<<<16, 128>>>(x);
    mlp_kernel<<<(NQ * NVAR) / 8, 256>>>(W1, b1, W2, b2);
    combine_kernel<<<(NQ * 64) / 256, 256>>>(b1, W2, b2, out);
}

// round 15
// speedup vs baseline: 2.1072x; 2.1072x over previous
#include <cuda_runtime.h>

// Problem constants (fixed by reference setup_inputs: B=2, N=1024, K=64, R=0.15)
#define NPTS   1024
#define NBATCH 2
#define NQ     (NBATCH * NPTS)     // 2048 queries
#define KNB    64
#define RADIUS2 0.0225f
#define NVAR   10                  // distinct nonzero diag variants

// Static device scratch (no allocation allowed)
__device__ float g_gp[NQ * 3 * KNB];        // SoA relative coords, zero-padded: [q][xyz][64]
__device__ int   g_cnt[NQ];                 // in-ball neighbor count per query
__device__ float g_m[NVAR * NQ * 64];       // per-variant per-query max, 64 ch

// diag variants: 4 full (weight 1 in combine), 6 single-axis (weight 2)
__device__ const float c_DX[NVAR] = { 1.f, 1.f,-1.f,-1.f,  1.f,-1.f, 0.f, 0.f, 0.f, 0.f };
__device__ const float c_DY[NVAR] = { 1.f,-1.f, 1.f,-1.f,  0.f, 0.f, 1.f,-1.f, 0.f, 0.f };
__device__ const float c_DZ[NVAR] = { 1.f,-1.f,-1.f, 1.f,  0.f, 0.f, 0.f, 0.f, 1.f,-1.f };

// ---- packed f32x2 helpers (Blackwell FFMA2: only reachable via PTX) -------
__device__ __forceinline__ unsigned long long ffma2(unsigned long long a,
                                                    unsigned long long b,
                                                    unsigned long long c) {
    unsigned long long d;
    asm("fma.rn.f32x2 %0, %1, %2, %3;" : "=l"(d) : "l"(a), "l"(b), "l"(c));
    return d;
}
__device__ __forceinline__ unsigned long long pack2(float lo, float hi) {
    unsigned long long d;
    asm("mov.b64 %0, {%1, %2};" : "=l"(d) : "f"(lo), "f"(hi));
    return d;
}
__device__ __forceinline__ float2 unpack2(unsigned long long v) {
    float lo, hi;
    asm("mov.b64 {%0, %1}, %2;" : "=f"(lo), "=f"(hi) : "l"(v));
    return make_float2(lo, hi);
}

// ---------------------------------------------------------------------------
// Kernel 1: ball gather — WARP per query (64x the parallelism of R13).
// Ballot-compaction appends in point-index order (deterministic). Set equality
// suffices for the downstream max-pool; exact serial top-64 fallback if cnt>64.
// Self (g=0, d2=0) is always in-ball, so zero padding is exact.
// ---------------------------------------------------------------------------
__global__ void __launch_bounds__(256) gather_kernel(const float* __restrict__ x) {
    __shared__ float ysx[NPTS], ysy[NPTS], ysz[NPTS];
    int warp = threadIdx.x >> 5;
    int lane = threadIdx.x & 31;
    int q = blockIdx.x * 8 + warp;          // 256 blocks x 8 warps = 2048 queries
    int b = q >> 10;                        // all 8 warps of a block share batch
    const float* xb = x + b * NPTS * 3;
    for (int i = threadIdx.x; i < NPTS; i += 256) {
        ysx[i] = xb[i * 3 + 0];
        ysy[i] = xb[i * 3 + 1];
        ysz[i] = xb[i * 3 + 2];
    }
    __syncthreads();

    int n = q & 1023;
    float qx = ysx[n], qy = ysy[n], qz = ysz[n];
    float* gq = g_gp + q * (3 * KNB);

    int base = 0;
    for (int m0 = 0; m0 < NPTS; m0 += 32) {
        int m = m0 + lane;
        float dx = ysx[m] - qx;
        float dy = ysy[m] - qy;
        float dz = ysz[m] - qz;
        // match XLA rounding at the radius boundary: no FMA contraction
        float d2 = __fadd_rn(__fadd_rn(__fmul_rn(dx, dx), __fmul_rn(dy, dy)),
                             __fmul_rn(dz, dz));
        bool hit = (d2 <= RADIUS2);
        unsigned bal = __ballot_sync(0xffffffffu, hit);
        int pos = base + __popc(bal & ((1u << lane) - 1u));
        if (hit && pos < KNB) {
            gq[pos]           = dx;
            gq[KNB + pos]     = dy;
            gq[2 * KNB + pos] = dz;
        }
        base += __popc(bal);
    }
    // zero-pad unused slots (exact: self g=0 is always a member)
    int cnt = base < KNB ? base : KNB;
    for (int t = cnt + lane; t < KNB; t += 32) {
        gq[t] = 0.0f; gq[KNB + t] = 0.0f; gq[2 * KNB + t] = 0.0f;
    }

    if (base > KNB && lane == 0) {
        // exact rare path: keep the 64 smallest d2 (never fires on this data)
        float dds[KNB];
        int c = 0;
        for (int m = 0; m < NPTS; m++) {
            float dx = ysx[m] - qx, dy = ysy[m] - qy, dz = ysz[m] - qz;
            float d2 = __fadd_rn(__fadd_rn(__fmul_rn(dx, dx), __fmul_rn(dy, dy)),
                                 __fmul_rn(dz, dz));
            if (d2 <= RADIUS2) {
                if (c < KNB) {
                    dds[c] = d2;
                    gq[c] = dx; gq[KNB + c] = dy; gq[2 * KNB + c] = dz;
                    c++;
                } else {
                    float mx = -1.0f; int mi = 0;
                    for (int t = 0; t < KNB; t++)
                        if (dds[t] > mx) { mx = dds[t]; mi = t; }
                    if (d2 < mx) {
                        dds[mi] = d2;
                        gq[mi] = dx; gq[KNB + mi] = dy; gq[2 * KNB + mi] = dz;
                    }
                }
            }
        }
    }
    if (lane == 0) g_cnt[q] = cnt;
}

// ---------------------------------------------------------------------------
// Kernel 2: per-(query, variant) MLP + neighbor max. One warp per (q, v).
// Phase 1 (lane = neighbor): compute h1[32] -> smem row (padded to 36 floats).
// Phase 2 (lane = output-channel pair): LDS.128 yields natively-packed f32x2
// h1 pairs; layer 2 runs as 32 FFMA2/neighbor with pre-packed W2 registers.
// Deterministic: no atomics, no cross-lane float reductions.
// ---------------------------------------------------------------------------
__global__ void __launch_bounds__(128, 4) mlp_kernel(const float* __restrict__ W1,
                                                     const float* __restrict__ b1,
                                                     const float* __restrict__ W2,
                                                     const float* __restrict__ b2) {
    __shared__ float4 sW1f4[32];                         // (w0,w1,w2,b1) per ch
    __shared__ __align__(16) float h1s[4][32][36];       // [warp][nbr][ch], padded

    int tid  = threadIdx.x;
    int lane = tid & 31;
    int wid  = tid >> 5;

    if (tid < 32)
        sW1f4[tid] = make_float4(W1[tid * 3 + 0], W1[tid * 3 + 1],
                                 W1[tid * 3 + 2], b1[tid]);
    __syncthreads();

    int w = blockIdx.x * 4 + wid;        // 0 .. 20479
    int q = w / NVAR;
    int v = w - q * NVAR;
    float sx = c_DX[v], sy = c_DY[v], sz = c_DZ[v];

    // W2 rows for output channels (lane, lane+32), as packed (c, c+1) pairs.
    unsigned long long w2a[16], w2b[16];
    {
        const ulonglong2* pa = reinterpret_cast<const ulonglong2*>(W2 + lane * 32);
        const ulonglong2* pb = reinterpret_cast<const ulonglong2*>(W2 + (lane + 32) * 32);
#pragma unroll
        for (int i = 0; i < 8; i++) {
            ulonglong2 ta = pa[i]; w2a[2 * i] = ta.x; w2a[2 * i + 1] = ta.y;
            ulonglong2 tb = pb[i]; w2b[2 * i] = tb.x; w2b[2 * i + 1] = tb.y;
        }
    }
    float bo0 = b2[lane], bo1 = b2[lane + 32];

    int cnt = g_cnt[q];
    const float* gq = g_gp + q * (3 * KNB);
    float (*hrow)[36] = h1s[wid];

    float m0 = 0.0f, m1 = 0.0f;          // relu outputs >= 0; self in set

    for (int j0 = 0; j0 < cnt; j0 += 32) {
        // ---- phase 1: lane = neighbor (g_gp zero-padded, safe to read < 64)
        int jj = j0 + lane;
        float px = sx * gq[jj];
        float py = sy * gq[KNB + jj];
        float pz = sz * gq[2 * KNB + jj];
#pragma unroll
        for (int c = 0; c < 32; c += 4) {
            float4 hv;
            float4 w0 = sW1f4[c + 0];
            hv.x = fmaxf(fmaf(px, w0.x, fmaf(py, w0.y, fmaf(pz, w0.z, w0.w))), 0.0f);
            float4 w1r = sW1f4[c + 1];
            hv.y = fmaxf(fmaf(px, w1r.x, fmaf(py, w1r.y, fmaf(pz, w1r.z, w1r.w))), 0.0f);
            float4 w2r = sW1f4[c + 2];
            hv.z = fmaxf(fmaf(px, w2r.x, fmaf(py, w2r.y, fmaf(pz, w2r.z, w2r.w))), 0.0f);
            float4 w3r = sW1f4[c + 3];
            hv.w = fmaxf(fmaf(px, w3r.x, fmaf(py, w3r.y, fmaf(pz, w3r.z, w3r.w))), 0.0f);
            *reinterpret_cast<float4*>(&hrow[lane][c]) = hv;
        }
        __syncwarp();

        // ---- phase 2: lane = output-channel pair; iterate real neighbors only
        int jend = cnt - j0; if (jend > 32) jend = 32;
        for (int j = 0; j < jend; j++) {
            const ulonglong2* hp = reinterpret_cast<const ulonglong2*>(&hrow[j][0]);
            unsigned long long acc0a = pack2(bo0, 0.0f), acc0b = 0ull;
            unsigned long long acc1a = pack2(bo1, 0.0f), acc1b = 0ull;
#pragma unroll
            for (int i = 0; i < 4; i++) {
                ulonglong2 ha = hp[2 * i];       // h pairs (8i, 8i+1), (8i+2, 8i+3)
                ulonglong2 hb = hp[2 * i + 1];
                acc0a = ffma2(ha.x, w2a[4 * i + 0], acc0a);
                acc1a = ffma2(ha.x, w2b[4 * i + 0], acc1a);
                acc0b = ffma2(ha.y, w2a[4 * i + 1], acc0b);
                acc1b = ffma2(ha.y, w2b[4 * i + 1], acc1b);
                acc0a = ffma2(hb.x, w2a[4 * i + 2], acc0a);
                acc1a = ffma2(hb.x, w2b[4 * i + 2], acc1a);
                acc0b = ffma2(hb.y, w2a[4 * i + 3], acc0b);
                acc1b = ffma2(hb.y, w2b[4 * i + 3], acc1b);
            }
            float2 s0a = unpack2(acc0a), s0b = unpack2(acc0b);
            float2 s1a = unpack2(acc1a), s1b = unpack2(acc1b);
            float r0 = (s0a.x + s0a.y) + (s0b.x + s0b.y);
            float r1 = (s1a.x + s1a.y) + (s1b.x + s1b.y);
            m0 = fmaxf(m0, fmaxf(r0, 0.0f));
            m1 = fmaxf(m1, fmaxf(r1, 0.0f));
        }
        __syncwarp();
    }

    float* mo = g_m + (v * NQ + q) * 64;
    mo[lane]      = m0;
    mo[lane + 32] = m1;
}

// ---------------------------------------------------------------------------
// Kernel 3: combine. f[b,o,n] = (8*c0[o] + sum_v w_v * m[v,q,o]) / 24
// c0 = relu(W2 relu(b1) + b2): output of the 8 zero-diagonal rotations.
// ---------------------------------------------------------------------------
__global__ void __launch_bounds__(256) combine_kernel(const float* __restrict__ b1,
                                                      const float* __restrict__ W2,
                                                      const float* __restrict__ b2,
                                                      float* __restrict__ out) {
    __shared__ float h1b[32];
    __shared__ float c0s[64];
    int tid = threadIdx.x;
    if (tid < 32) h1b[tid] = fmaxf(b1[tid], 0.0f);
    __syncthreads();
    if (tid < 64) {
        float a = b2[tid];
#pragma unroll
        for (int c = 0; c < 32; c++) a = fmaf(W2[tid * 32 + c], h1b[c], a);
        c0s[tid] = 8.0f * fmaxf(a, 0.0f);
    }
    __syncthreads();

    const float WV[NVAR] = { 1.f, 1.f, 1.f, 1.f, 2.f, 2.f, 2.f, 2.f, 2.f, 2.f };

    int i = blockIdx.x * 256 + tid;      // 0 .. 131071 (= NQ*64)
    int q = i >> 6;
    int o = i & 63;
    float f = c0s[o];
#pragma unroll
    for (int v = 0; v < NVAR; v++)
        f += WV[v] * g_m[(v * NQ + q) * 64 + o];

    int b = q >> 10;
    int n = q & 1023;
    out[(b * 64 + o) * NPTS + n] = f * (1.0f / 24.0f);
}

// ---------------------------------------------------------------------------
extern "C" void kernel_launch(void* const* d_in, const int* in_sizes, int n_in,
                              void* d_out, int out_size) {
    const float* x  = (const float*)d_in[0];   // [2,1024,3]
    const float* W1 = (const float*)d_in[1];   // [32,3]
    const float* b1 = (const float*)d_in[2];   // [32]
    const float* W2 = (const float*)d_in[3];   // [64,32]
    const float* b2 = (const float*)d_in[4];   // [64]
    float* out = (float*)d_out;                // [2,64,1024]

    gather_kernel<<<NQ / 8, 256>>>(x);
    mlp_kernel<<<(NQ * NVAR) / 4, 128>>>(W1, b1, W2, b2);
    combine_kernel<<<(NQ * 64) / 256, 256>>>(b1, W2, b2, out);
}